// round 16
// baseline (speedup 1.0000x reference)
#include <cuda_runtime.h>
#include <cstddef>
#include <math_constants.h>

#define NNODES 4096
#define NB 4
#define BN (NNODES * NB)
#define DFEAT 240
#define FXSTRIDE 256
#define KNN 8
#define NBINS 4096            // 16^3 morton bins
#define NGROUP 32             // groups per batch (4096/128)
#define GRP 128               // points per group

// Scratch (allocation-free rule: __device__ globals)
__device__ int    g_knn[BN * KNN];
__device__ float4 g_c4[BN];                       // (x,y,z,|c|^2/2) original order
__device__ float  g_fx[(size_t)BN * FXSTRIDE];    // repacked features
// Fused (W @ L) matrices, output scales baked in
__device__ float g_WL0[32 * 64];
__device__ float g_WL1a[64 * 32];
__device__ float g_WL1b[16 * 32];
__device__ float g_WL2[32 * 16];
// Morton sort + groups
__device__ unsigned g_bbox[NB][6];
__device__ int      g_cnt[NB][NBINS];
__device__ int      g_ctr[NB][NBINS];
__device__ int      g_cellstart[NB][NBINS + 1];
__device__ unsigned short g_pcell[BN];
__device__ float4   g_pts4[BN];                   // morton-sorted (x,y,z,h)
__device__ int      g_pidx[BN];                   // sorted -> original flat id
__device__ float4   g_glo[NB * NGROUP];           // group AABB min
__device__ float4   g_ghi[NB * NGROUP];           // group AABB max

__device__ __forceinline__ unsigned fenc(float f) {
    unsigned u = __float_as_uint(f);
    return (u & 0x80000000u) ? ~u : (u | 0x80000000u);
}
__device__ __forceinline__ float fdec(unsigned u) {
    return __uint_as_float((u & 0x80000000u) ? (u ^ 0x80000000u) : ~u);
}

// T[a][k] = (Cm[a] . ev)[k]
__device__ __forceinline__ void compute_T(float ex, float ey, float ez, float T[5][3]) {
    const float sc = 0.31622776601683794f;
    const float tc = 0.18257418583505536f;
    T[0][0] = sc * ey;  T[0][1] = sc * ex;   T[0][2] = 0.f;
    T[1][0] = sc * ez;  T[1][1] = 0.f;       T[1][2] = sc * ex;
    T[2][0] = 0.f;      T[2][1] = sc * ez;   T[2][2] = sc * ey;
    T[3][0] = sc * ex;  T[3][1] = -sc * ey;  T[3][2] = 0.f;
    T[4][0] = -tc * ex; T[4][1] = -tc * ey;  T[4][2] = 2.f * tc * ez;
}

// ============================================================================
// fuse W@L + zero hist/ctr + seed bbox.
// ============================================================================
__global__ __launch_bounds__(256) void fuse_kernel(
    const float* __restrict__ W1, const float* __restrict__ W2,
    const float* __restrict__ W3, const float* __restrict__ W4,
    const float* __restrict__ L0, const float* __restrict__ L1,
    const float* __restrict__ L2) {
    const float c1 = 0.11180339887498949f;
    const float c2 = 0.10206207261596575f;
    const float c3 = 0.39528470752104744f;
    const float c4 = 0.19364916731037085f;
    const float is32 = 0.17677669529663687f;
    int idx = blockIdx.x * 256 + threadIdx.x;
    int* cntf = &g_cnt[0][0];
    int* ctrf = &g_ctr[0][0];
    for (int k = idx; k < NB * NBINS; k += 5120) { cntf[k] = 0; ctrf[k] = 0; }
    if (idx < NB * 6) {
        int b = idx / 6, c = idx % 6;
        g_bbox[b][c] = (c < 3) ? 0xFFFFFFFFu : 0u;
    }
    if (idx < 2048) {
        int u = idx >> 6, w2 = idx & 63;
        float acc = 0.f;
        for (int w = 0; w < 64; w++) acc = fmaf(W2[u * 64 + w], L0[w * 64 + w2], acc);
        g_WL0[idx] = (c2 * 0.125f) * acc;
    } else if (idx < 4096) {
        int t = idx - 2048, u = t >> 5, w2 = t & 31;
        float acc = 0.f;
        for (int w = 0; w < 32; w++) acc = fmaf(W1[u * 32 + w], L1[w * 32 + w2], acc);
        g_WL1a[t] = (c1 * is32) * acc;
    } else if (idx < 4608) {
        int t = idx - 4096, u = t >> 5, w2 = t & 31;
        float acc = 0.f;
        for (int w = 0; w < 32; w++) acc = fmaf(W4[u * 32 + w], L1[w * 32 + w2], acc);
        g_WL1b[t] = (c4 * is32) * acc;
    } else if (idx < 5120) {
        int t = idx - 4608, u = t >> 4, w2 = t & 15;
        float acc = 0.f;
        for (int w = 0; w < 16; w++) acc = fmaf(W3[u * 16 + w], L2[w * 16 + w2], acc);
        g_WL2[t] = (c3 * 0.25f) * acc;
    }
}

// ============================================================================
// repack features (warp per node) + build g_c4 (proven round-10 version).
// ============================================================================
__global__ __launch_bounds__(256) void repack_kernel(
    const float* __restrict__ feats, const float* __restrict__ coords) {
    int warp = threadIdx.x >> 5, lane = threadIdx.x & 31;
    int node = blockIdx.x * 8 + warp;
    const float* f = feats + (size_t)node * DFEAT;
    float* o = g_fx + (size_t)node * FXSTRIDE;
    float4 A;
    A.x = f[lane];
    A.y = f[64 + 3 * lane];
    A.z = f[64 + 3 * lane + 1];
    A.w = f[64 + 3 * lane + 2];
    *(float4*)(o + 4 * lane) = A;
    o[128 + lane] = f[32 + lane];
    if (lane < 16) {
        float4 X;
        X.x = f[160 + 5 * lane];
        X.y = f[160 + 5 * lane + 1];
        X.z = f[160 + 5 * lane + 2];
        X.w = f[160 + 5 * lane + 3];
        *(float4*)(o + 160 + 4 * lane) = X;
        o[224 + lane] = f[160 + 5 * lane + 4];
    }
    if (threadIdx.x < 8) {
        int n2 = blockIdx.x * 8 + threadIdx.x;
        float x = coords[3 * n2], y = coords[3 * n2 + 1], z = coords[3 * n2 + 2];
        g_c4[n2] = make_float4(x, y, z, 0.5f * fmaf(x, x, fmaf(y, y, z * z)));
    }
}

// ============================================================================
// bbox per batch (warp reduce + encoded atomics).
// ============================================================================
__global__ __launch_bounds__(256) void bbox_kernel(const float* __restrict__ coords) {
    const unsigned FULL = 0xffffffffu;
    int i = blockIdx.x * 256 + threadIdx.x;
    int b = i >> 12;
    float x = coords[3 * i], y = coords[3 * i + 1], z = coords[3 * i + 2];
    float mnx = x, mny = y, mnz = z, mxx = x, mxy = y, mxz = z;
#pragma unroll
    for (int off = 16; off >= 1; off >>= 1) {
        mnx = fminf(mnx, __shfl_xor_sync(FULL, mnx, off));
        mny = fminf(mny, __shfl_xor_sync(FULL, mny, off));
        mnz = fminf(mnz, __shfl_xor_sync(FULL, mnz, off));
        mxx = fmaxf(mxx, __shfl_xor_sync(FULL, mxx, off));
        mxy = fmaxf(mxy, __shfl_xor_sync(FULL, mxy, off));
        mxz = fmaxf(mxz, __shfl_xor_sync(FULL, mxz, off));
    }
    if ((threadIdx.x & 31) == 0) {
        atomicMin(&g_bbox[b][0], fenc(mnx));
        atomicMin(&g_bbox[b][1], fenc(mny));
        atomicMin(&g_bbox[b][2], fenc(mnz));
        atomicMax(&g_bbox[b][3], fenc(mxx));
        atomicMax(&g_bbox[b][4], fenc(mxy));
        atomicMax(&g_bbox[b][5], fenc(mxz));
    }
}

__device__ __forceinline__ int cc16(float x, float x0, float ih) {
    int c = (int)((x - x0) * ih);
    return min(15, max(0, c));
}

// ============================================================================
// morton code (4 bits/axis) histogram.
// ============================================================================
__global__ __launch_bounds__(256) void mort_kernel(const float* __restrict__ coords) {
    int i = blockIdx.x * 256 + threadIdx.x;
    int b = i >> 12;
    float x0 = fdec(g_bbox[b][0]), y0 = fdec(g_bbox[b][1]), z0 = fdec(g_bbox[b][2]);
    float x1 = fdec(g_bbox[b][3]), y1 = fdec(g_bbox[b][4]), z1 = fdec(g_bbox[b][5]);
    float ihx = 16.f / (x1 - x0 + 1e-4f);
    float ihy = 16.f / (y1 - y0 + 1e-4f);
    float ihz = 16.f / (z1 - z0 + 1e-4f);
    float x = coords[3 * i], y = coords[3 * i + 1], z = coords[3 * i + 2];
    int cx = cc16(x, x0, ihx), cy = cc16(y, y0, ihy), cz = cc16(z, z0, ihz);
    unsigned m = 0;
#pragma unroll
    for (int k = 0; k < 4; k++) {
        m |= ((cx >> k) & 1) << (3 * k);
        m |= ((cy >> k) & 1) << (3 * k + 1);
        m |= ((cz >> k) & 1) << (3 * k + 2);
    }
    g_pcell[i] = (unsigned short)m;
    atomicAdd(&g_cnt[b][m], 1);
}

// ============================================================================
// prefix scan of 4096 bins per batch (1 block / batch).
// ============================================================================
__global__ __launch_bounds__(1024) void scan_kernel() {
    __shared__ int part[1024];
    int b = blockIdx.x, tid = threadIdx.x;
    int base = tid * 4;
    int loc[4];
    int s = 0;
#pragma unroll
    for (int k = 0; k < 4; k++) { loc[k] = s; s += g_cnt[b][base + k]; }
    part[tid] = s;
    __syncthreads();
    for (int off = 1; off < 1024; off <<= 1) {
        int v = (tid >= off) ? part[tid - off] : 0;
        __syncthreads();
        part[tid] += v;
        __syncthreads();
    }
    int excl = tid ? part[tid - 1] : 0;
#pragma unroll
    for (int k = 0; k < 4; k++) g_cellstart[b][base + k] = excl + loc[k];
    if (tid == 1023) g_cellstart[b][NBINS] = part[1023];
}

// ============================================================================
// scatter into morton-sorted arrays.
// ============================================================================
__global__ __launch_bounds__(256) void scatter_kernel(const float* __restrict__ coords) {
    int i = blockIdx.x * 256 + threadIdx.x;
    int b = i >> 12;
    int cell = g_pcell[i];
    int pos = g_cellstart[b][cell] + atomicAdd(&g_ctr[b][cell], 1);
    float x = coords[3 * i], y = coords[3 * i + 1], z = coords[3 * i + 2];
    int sp = (b << 12) + pos;
    g_pts4[sp] = make_float4(x, y, z, 0.5f * fmaf(x, x, fmaf(y, y, z * z)));
    g_pidx[sp] = i;
}

// ============================================================================
// group AABBs: warp per group (128 points, 4/lane, shfl reduce).
// ============================================================================
__global__ __launch_bounds__(256) void gbox_kernel() {
    const unsigned FULL = 0xffffffffu;
    int w = (blockIdx.x << 3) + (threadIdx.x >> 5);   // 0..127 flat group
    int lane = threadIdx.x & 31;
    int base = w << 7;
    float mnx = CUDART_INF_F, mny = CUDART_INF_F, mnz = CUDART_INF_F;
    float mxx = -CUDART_INF_F, mxy = -CUDART_INF_F, mxz = -CUDART_INF_F;
#pragma unroll
    for (int t = 0; t < 4; t++) {
        float4 c = g_pts4[base + (t << 5) + lane];
        mnx = fminf(mnx, c.x); mxx = fmaxf(mxx, c.x);
        mny = fminf(mny, c.y); mxy = fmaxf(mxy, c.y);
        mnz = fminf(mnz, c.z); mxz = fmaxf(mxz, c.z);
    }
#pragma unroll
    for (int off = 16; off >= 1; off >>= 1) {
        mnx = fminf(mnx, __shfl_xor_sync(FULL, mnx, off));
        mny = fminf(mny, __shfl_xor_sync(FULL, mny, off));
        mnz = fminf(mnz, __shfl_xor_sync(FULL, mnz, off));
        mxx = fmaxf(mxx, __shfl_xor_sync(FULL, mxx, off));
        mxy = fmaxf(mxy, __shfl_xor_sync(FULL, mxy, off));
        mxz = fmaxf(mxz, __shfl_xor_sync(FULL, mxz, off));
    }
    if (lane == 0) {
        g_glo[w] = make_float4(mnx, mny, mnz, 0.f);
        g_ghi[w] = make_float4(mxx, mxy, mxz, 0.f);
    }
}

// ============================================================================
// kNN: warp per query, BEST-FIRST over 32 Morton groups. Lane g holds group
// g's exact AABB lower-bound distance bd2 (static). Loop: shfl-argmin over
// unvisited bd2; stop when min bd2 exceeds current 9th-best d^2 (+ slack) —
// rigorous, since the AABB contains all group points. Scanned groups use the
// proven round-10 warp-collective top-9 insert (lane 0 = self via strict
// unique min score -|q|^2/2; lanes 1..8 = true top-8).
// ============================================================================
__global__ __launch_bounds__(256) void knn_kernel() {
    const unsigned FULL = 0xffffffffu;
    int b = blockIdx.y;
    int warp = threadIdx.x >> 5, lane = threadIdx.x & 31;
    int q = blockIdx.x * 8 + warp;
    int qflat = (b << 12) + q;

    float4 qc = g_c4[qflat];
    float nqx = -qc.x, nqy = -qc.y, nqz = -qc.z;

    // lane g = group g of this batch: static AABB bound
    int gw = (b << 5) + lane;
    float4 lo = g_glo[gw], hi = g_ghi[gw];
    float dx = fmaxf(0.f, fmaxf(lo.x - qc.x, qc.x - hi.x));
    float dy = fmaxf(0.f, fmaxf(lo.y - qc.y, qc.y - hi.y));
    float dz = fmaxf(0.f, fmaxf(lo.z - qc.z, qc.z - hi.z));
    float bd2 = fmaf(dx, dx, fmaf(dy, dy, dz * dz));  // INF'd once visited

    float v = CUDART_INF_F;
    int  vid = 0x7fffffff;
    float worst = CUDART_INF_F;
    int bbase = b << 12;

    while (true) {
        // warp argmin over unvisited groups (consistent tie rule)
        float mv = bd2; int mg = lane;
#pragma unroll
        for (int off = 16; off >= 1; off >>= 1) {
            float ov = __shfl_xor_sync(FULL, mv, off);
            int   og = __shfl_xor_sync(FULL, mg, off);
            if (ov < mv || (ov == mv && og < mg)) { mv = ov; mg = og; }
        }
        float wd2 = 2.f * (worst + qc.w);             // current 9th-best d^2
        if (!(mv <= wd2 * 1.0001f + 1e-2f)) break;    // prune (INF mv also exits)
        if (lane == mg) bd2 = CUDART_INF_F;           // mark visited

        int base = bbase + (mg << 7);
        float d[4];
#pragma unroll
        for (int t = 0; t < 4; t++) {
            float4 c = g_pts4[base + (t << 5) + lane];
            d[t] = fmaf(nqx, c.x, fmaf(nqy, c.y, fmaf(nqz, c.z, c.w)));
        }
#pragma unroll
        for (int t = 0; t < 4; t++) {
            unsigned mask = __ballot_sync(FULL, d[t] < worst);
            int jt = base + (t << 5);
            while (mask) {
                int src = __ffs(mask) - 1; mask &= mask - 1;
                float nb = __shfl_sync(FULL, d[t], src);
                if (nb < worst) {                     // warp-uniform recheck
                    int ib = g_pidx[jt + src];        // original flat id (uniform)
                    unsigned gt = __ballot_sync(FULL, (lane < 9) && (v > nb));
                    int p = __ffs(gt) - 1;            // nonzero: lane8 holds worst>nb
                    float vup = __shfl_up_sync(FULL, v, 1);
                    int  iup  = __shfl_up_sync(FULL, vid, 1);
                    if (lane == p)                 { v = nb;  vid = ib;  }
                    else if (lane > p && lane < 9) { v = vup; vid = iup; }
                    worst = __shfl_sync(FULL, v, 8);
                    mask &= __ballot_sync(FULL, d[t] < worst);  // prune stale
                }
            }
        }
    }

    if (lane >= 1 && lane < 9)                        // lane 0 = self; drop it
        g_knn[qflat * KNN + (lane - 1)] = vid;
}

// ============================================================================
// fused aggregation (round-10 version: 48 regs, measured-stable 47us).
// ============================================================================
__global__ __launch_bounds__(256) void agg_kernel(float* __restrict__ out) {
    __shared__ float sWL0[2048], sWL1a[2048], sWL1b[512], sWL2[512];
    __shared__ float sag[8][440];
    for (int k = threadIdx.x; k < 2048; k += 256) { sWL0[k] = g_WL0[k]; sWL1a[k] = g_WL1a[k]; }
    for (int k = threadIdx.x; k < 512;  k += 256) { sWL1b[k] = g_WL1b[k]; sWL2[k] = g_WL2[k]; }

    int warp = threadIdx.x >> 5, lane = threadIdx.x & 31;
    int node = (blockIdx.x << 3) + warp;
    float4 qc = g_c4[node];

    int4 n0 = *(const int4*)(g_knn + node * KNN);
    int4 n1 = *(const int4*)(g_knn + node * KNN + 4);
    int nbr[8] = {n0.x, n0.y, n0.z, n0.w, n1.x, n1.y, n1.z, n1.w};
    float ex[8], ey[8], ez[8];
#pragma unroll
    for (int r = 0; r < 8; r++) {
        float4 cn = g_c4[nbr[r]];
        ex[r] = cn.x - qc.x;
        ey[r] = cn.y - qc.y;
        ez[r] = cn.z - qc.z;
    }

    float a0 = 0.f;
    float a1a0[3] = {0.f, 0.f, 0.f};
    float a1a1[3] = {0.f, 0.f, 0.f};
    float a1b[3]  = {0.f, 0.f, 0.f};
    float a2[5]   = {0.f, 0.f, 0.f, 0.f, 0.f};

#pragma unroll
    for (int r = 0; r < KNN; r++) {
        const float* f = g_fx + (size_t)nbr[r] * FXSTRIDE;
        float4 A = *(const float4*)(f + 4 * lane);
        float f0b = f[128 + lane];
        float4 X = make_float4(0.f, 0.f, 0.f, 0.f);
        float x4 = 0.f;
        if (lane < 16) {
            X  = *(const float4*)(f + 160 + 4 * lane);
            x4 = f[224 + lane];
        }

        float T[5][3];
        compute_T(ex[r], ey[r], ez[r], T);
        float e[3] = {ex[r], ey[r], ez[r]};
        float x1v[3] = {A.y, A.z, A.w};
        float x2v[5] = {X.x, X.y, X.z, X.w, x4};

#pragma unroll
        for (int k = 0; k < 3; k++) {
            a1a0[k] = fmaf(A.x, e[k], a1a0[k]);
            a1a1[k] = fmaf(f0b, e[k], a1a1[k]);
        }
#pragma unroll
        for (int i = 0; i < 3; i++) a0 = fmaf(x1v[i], e[i], a0);
#pragma unroll
        for (int a = 0; a < 5; a++)
#pragma unroll
            for (int i = 0; i < 3; i++) a2[a] = fmaf(x1v[i], T[a][i], a2[a]);
        if (lane < 16) {
#pragma unroll
            for (int a = 0; a < 5; a++)
#pragma unroll
                for (int k = 0; k < 3; k++) a1b[k] = fmaf(x2v[a], T[a][k], a1b[k]);
        }
    }

    __syncthreads();

    float* ag = sag[warp];
    ag[lane] = a0;
#pragma unroll
    for (int k = 0; k < 3; k++) {
        ag[32 + 3 * lane + k]        = a1a0[k];
        ag[32 + 3 * (lane + 32) + k] = a1a1[k];
    }
    if (lane < 16) {
#pragma unroll
        for (int k = 0; k < 3; k++) ag[224 + 3 * lane + k] = a1b[k];
    }
#pragma unroll
    for (int a = 0; a < 5; a++) ag[272 + 5 * lane + a] = a2[a];
    __syncwarp();

    float* o = out + (size_t)node * DFEAT;
    {
        float y0 = 0.f, y1v = 0.f;
#pragma unroll
        for (int u = 0; u < 32; u++) {
            float av = ag[u];
            y0  = fmaf(av, sWL0[u * 64 + 2 * lane],     y0);
            y1v = fmaf(av, sWL0[u * 64 + 2 * lane + 1], y1v);
        }
        o[2 * lane]     = y0;
        o[2 * lane + 1] = y1v;
    }
    {
        float y[3] = {0.f, 0.f, 0.f};
#pragma unroll
        for (int u = 0; u < 64; u++) {
            float lw = sWL1a[u * 32 + lane];
#pragma unroll
            for (int k = 0; k < 3; k++) y[k] = fmaf(ag[32 + 3 * u + k], lw, y[k]);
        }
#pragma unroll
        for (int u = 0; u < 16; u++) {
            float lw = sWL1b[u * 32 + lane];
#pragma unroll
            for (int k = 0; k < 3; k++) y[k] = fmaf(ag[224 + 3 * u + k], lw, y[k]);
        }
#pragma unroll
        for (int k = 0; k < 3; k++) o[64 + 3 * lane + k] = y[k];
    }
    if (lane < 16) {
        float y[5] = {0.f, 0.f, 0.f, 0.f, 0.f};
#pragma unroll
        for (int u = 0; u < 32; u++) {
            float lw = sWL2[u * 16 + lane];
#pragma unroll
            for (int a = 0; a < 5; a++) y[a] = fmaf(ag[272 + 5 * u + a], lw, y[a]);
        }
#pragma unroll
        for (int a = 0; a < 5; a++) o[160 + 5 * lane + a] = y[a];
    }
}

// ============================================================================
extern "C" void kernel_launch(void* const* d_in, const int* in_sizes, int n_in,
                              void* d_out, int out_size) {
    const float* feats  = (const float*)d_in[0];
    const float* coords = (const float*)d_in[1];
    const float* W1 = (const float*)d_in[2];
    const float* W2 = (const float*)d_in[3];
    const float* W3 = (const float*)d_in[4];
    const float* W4 = (const float*)d_in[5];
    const float* L0 = (const float*)d_in[6];
    const float* L1 = (const float*)d_in[7];
    const float* L2 = (const float*)d_in[8];
    float* out = (float*)d_out;

    fuse_kernel<<<20, 256>>>(W1, W2, W3, W4, L0, L1, L2);   // WL + grid init
    repack_kernel<<<BN / 8, 256>>>(feats, coords);
    bbox_kernel<<<BN / 256, 256>>>(coords);
    mort_kernel<<<BN / 256, 256>>>(coords);
    scan_kernel<<<NB, 1024>>>();
    scatter_kernel<<<BN / 256, 256>>>(coords);
    gbox_kernel<<<16, 256>>>();
    knn_kernel<<<dim3(NNODES / 8, NB), 256>>>();
    agg_kernel<<<BN / 8, 256>>>(out);
}

// round 17
// speedup vs baseline: 1.3124x; 1.3124x over previous
#include <cuda_runtime.h>
#include <cstddef>
#include <math_constants.h>

#define NNODES 4096
#define NB 4
#define BN (NNODES * NB)
#define DFEAT 240
#define FXSTRIDE 256
#define KNN 8
#define KTHREADS 512
#define KWARPS (KTHREADS / 32)

// Scratch (allocation-free rule: __device__ globals)
__device__ int    g_knn[BN * KNN];
__device__ float4 g_c4[BN];                       // (x,y,z,|c|^2/2)
__device__ float  g_fx[(size_t)BN * FXSTRIDE];    // repacked features
// Fused (W @ L) matrices, output scales baked in
__device__ float g_WL0[32 * 64];
__device__ float g_WL1a[64 * 32];
__device__ float g_WL1b[16 * 32];
__device__ float g_WL2[32 * 16];

// T[a][k] = (Cm[a] . ev)[k]
__device__ __forceinline__ void compute_T(float ex, float ey, float ez, float T[5][3]) {
    const float sc = 0.31622776601683794f;
    const float tc = 0.18257418583505536f;
    T[0][0] = sc * ey;  T[0][1] = sc * ex;   T[0][2] = 0.f;
    T[1][0] = sc * ez;  T[1][1] = 0.f;       T[1][2] = sc * ex;
    T[2][0] = 0.f;      T[2][1] = sc * ez;   T[2][2] = sc * ey;
    T[3][0] = sc * ex;  T[3][1] = -sc * ey;  T[3][2] = 0.f;
    T[4][0] = -tc * ex; T[4][1] = -tc * ey;  T[4][2] = 2.f * tc * ez;
}

// ============================================================================
// Kernel 0: repack features per node (warp per node) + build g_c4.
// Blocks 0..19 ALSO compute the fused W@L matrices (runs in parallel with the
// other blocks' repack work; saves a kernel launch).
// Layout per node (stride 256 floats):
//   [4u .. 4u+4)   = (x0[u], x1[u][0], x1[u][1], x1[u][2])   u<32  (LDG.128)
//   [128 + u)      = x0[32+u]                                 u<32
//   [160 + 4u ..)  = x2[u][0..3]                              u<16  (LDG.128)
//   [224 + u)      = x2[u][4]                                 u<16
// ============================================================================
__global__ __launch_bounds__(256) void repack_kernel(
    const float* __restrict__ feats, const float* __restrict__ coords,
    const float* __restrict__ W1, const float* __restrict__ W2,
    const float* __restrict__ W3, const float* __restrict__ W4,
    const float* __restrict__ L0, const float* __restrict__ L1,
    const float* __restrict__ L2) {
    int warp = threadIdx.x >> 5, lane = threadIdx.x & 31;
    int node = blockIdx.x * 8 + warp;
    const float* f = feats + (size_t)node * DFEAT;
    float* o = g_fx + (size_t)node * FXSTRIDE;
    float4 A;
    A.x = f[lane];
    A.y = f[64 + 3 * lane];
    A.z = f[64 + 3 * lane + 1];
    A.w = f[64 + 3 * lane + 2];
    *(float4*)(o + 4 * lane) = A;
    o[128 + lane] = f[32 + lane];
    if (lane < 16) {
        float4 X;
        X.x = f[160 + 5 * lane];
        X.y = f[160 + 5 * lane + 1];
        X.z = f[160 + 5 * lane + 2];
        X.w = f[160 + 5 * lane + 3];
        *(float4*)(o + 160 + 4 * lane) = X;
        o[224 + lane] = f[160 + 5 * lane + 4];
    }
    if (threadIdx.x < 8) {                        // g_c4 for this block's 8 nodes
        int n2 = blockIdx.x * 8 + threadIdx.x;
        float x = coords[3 * n2], y = coords[3 * n2 + 1], z = coords[3 * n2 + 2];
        g_c4[n2] = make_float4(x, y, z, 0.5f * fmaf(x, x, fmaf(y, y, z * z)));
    }

    // ---- fused W@L computation on blocks 0..19 (5120 outputs, 1/thread)
    if (blockIdx.x < 20) {
        const float c1 = 0.11180339887498949f;
        const float c2 = 0.10206207261596575f;
        const float c3 = 0.39528470752104744f;
        const float c4 = 0.19364916731037085f;
        const float is32 = 0.17677669529663687f;
        int idx = blockIdx.x * 256 + threadIdx.x;
        if (idx < 2048) {                         // WL0 = W2@L0 : (32,64)
            int u = idx >> 6, w2 = idx & 63;
            float acc = 0.f;
            for (int w = 0; w < 64; w++) acc = fmaf(W2[u * 64 + w], L0[w * 64 + w2], acc);
            g_WL0[idx] = (c2 * 0.125f) * acc;
        } else if (idx < 4096) {                  // WL1a = W1@L1 : (64,32)
            int t = idx - 2048, u = t >> 5, w2 = t & 31;
            float acc = 0.f;
            for (int w = 0; w < 32; w++) acc = fmaf(W1[u * 32 + w], L1[w * 32 + w2], acc);
            g_WL1a[t] = (c1 * is32) * acc;
        } else if (idx < 4608) {                  // WL1b = W4@L1 : (16,32)
            int t = idx - 4096, u = t >> 5, w2 = t & 31;
            float acc = 0.f;
            for (int w = 0; w < 32; w++) acc = fmaf(W4[u * 32 + w], L1[w * 32 + w2], acc);
            g_WL1b[t] = (c4 * is32) * acc;
        } else {                                  // WL2 = W3@L2 : (32,16)
            int t = idx - 4608, u = t >> 4, w2 = t & 15;
            float acc = 0.f;
            for (int w = 0; w < 16; w++) acc = fmaf(W3[u * 16 + w], L2[w * 16 + w2], acc);
            g_WL2[t] = (c3 * 0.25f) * acc;
        }
    }
}

// ============================================================================
// Kernel 1: kNN, WARP per query, TOP-9 distributed across lanes 0..8 (sorted
// ascending; lane 8 = worst). No per-candidate self-exclusion: the query
// itself has the strict unique minimum score (-|q|^2/2), so it provably ends
// in lane 0; lanes 1..8 are the true top-8 neighbors. Per step: 128
// candidates (4/lane) from shared tile, one warp-uniform vote; inserts are
// warp-uniform shfl-shift ops. Tie = earliest index — matches jax.lax.top_k.
// (Round-10 champion: all six attempted redesigns regressed.)
// ============================================================================
__global__ __launch_bounds__(KTHREADS) void knn_kernel() {
    __shared__ float4 tile[2048];                 // 32KB (chunked: 2 x 2048)
    const unsigned FULL = 0xffffffffu;
    int b = blockIdx.y;
    int warp = threadIdx.x >> 5, lane = threadIdx.x & 31;
    int q = blockIdx.x * KWARPS + warp;           // query within batch
    int qflat = b * NNODES + q;

    float4 qc = g_c4[qflat];
    float nqx = -qc.x, nqy = -qc.y, nqz = -qc.z;

    float v  = CUDART_INF_F;                      // lane's slot of the top-9 (lanes 0..8)
    int  vid = 0x7fffffff;
    float worst = CUDART_INF_F;                   // = v at lane 8

    for (int ch = 0; ch < 2; ch++) {
        int cbase = ch << 11;
        __syncthreads();
        for (int k = threadIdx.x; k < 2048; k += KTHREADS)
            tile[k] = g_c4[b * NNODES + cbase + k];
        __syncthreads();

        for (int s = 0; s < 2048; s += 128) {
            float d[4];
#pragma unroll
            for (int t = 0; t < 4; t++) {
                float4 c = tile[s + (t << 5) + lane];
                d[t] = fmaf(nqx, c.x, fmaf(nqy, c.y, fmaf(nqz, c.z, c.w)));
            }
            float m = fminf(fminf(d[0], d[1]), fminf(d[2], d[3]));
            if (__any_sync(FULL, m < worst)) {
#pragma unroll
                for (int t = 0; t < 4; t++) {
                    unsigned mask = __ballot_sync(FULL, d[t] < worst);
                    int jbase = cbase + s + (t << 5);
                    while (mask) {
                        int src = __ffs(mask) - 1; mask &= mask - 1;
                        float nb = __shfl_sync(FULL, d[t], src);
                        if (nb < worst) {                 // warp-uniform recheck
                            int ib = jbase + src;         // arithmetic id recovery
                            unsigned gt = __ballot_sync(FULL, (lane < 9) && (v > nb));
                            int p = __ffs(gt) - 1;        // nonzero: lane8 has v=worst>nb
                            float vup = __shfl_up_sync(FULL, v, 1);
                            int  iup  = __shfl_up_sync(FULL, vid, 1);
                            if (lane == p)                 { v = nb;  vid = ib;  }
                            else if (lane > p && lane < 9) { v = vup; vid = iup; }
                            worst = __shfl_sync(FULL, v, 8);
                        }
                    }
                }
            }
        }
    }

    if (lane >= 1 && lane < 9)                    // lane 0 = self; drop it
        g_knn[qflat * KNN + (lane - 1)] = b * NNODES + vid;
}

// ============================================================================
// Kernel 2: fused aggregation (round-10 version: 48 regs, measured-stable).
// Warp per node. Vectorized coalesced gathers from packed g_fx; neighbor ids
// + coords front-batched. Fused WL linears from shared.
// ============================================================================
__global__ __launch_bounds__(256) void agg_kernel(float* __restrict__ out) {
    __shared__ float sWL0[2048], sWL1a[2048], sWL1b[512], sWL2[512];
    __shared__ float sag[8][440];
    for (int k = threadIdx.x; k < 2048; k += 256) { sWL0[k] = g_WL0[k]; sWL1a[k] = g_WL1a[k]; }
    for (int k = threadIdx.x; k < 512;  k += 256) { sWL1b[k] = g_WL1b[k]; sWL2[k] = g_WL2[k]; }

    int warp = threadIdx.x >> 5, lane = threadIdx.x & 31;
    int node = (blockIdx.x << 3) + warp;
    float4 qc = g_c4[node];

    // front-batch neighbor ids (32B aligned) and edge vectors
    int4 n0 = *(const int4*)(g_knn + node * KNN);
    int4 n1 = *(const int4*)(g_knn + node * KNN + 4);
    int nbr[8] = {n0.x, n0.y, n0.z, n0.w, n1.x, n1.y, n1.z, n1.w};
    float ex[8], ey[8], ez[8];
#pragma unroll
    for (int r = 0; r < 8; r++) {
        float4 cn = g_c4[nbr[r]];
        ex[r] = cn.x - qc.x;
        ey[r] = cn.y - qc.y;
        ez[r] = cn.z - qc.z;
    }

    float a0 = 0.f;
    float a1a0[3] = {0.f, 0.f, 0.f};
    float a1a1[3] = {0.f, 0.f, 0.f};
    float a1b[3]  = {0.f, 0.f, 0.f};
    float a2[5]   = {0.f, 0.f, 0.f, 0.f, 0.f};

#pragma unroll
    for (int r = 0; r < KNN; r++) {
        const float* f = g_fx + (size_t)nbr[r] * FXSTRIDE;
        float4 A = *(const float4*)(f + 4 * lane);        // x0a, x1[0..2]
        float f0b = f[128 + lane];                        // x0b
        float4 X = make_float4(0.f, 0.f, 0.f, 0.f);
        float x4 = 0.f;
        if (lane < 16) {
            X  = *(const float4*)(f + 160 + 4 * lane);    // x2[0..3]
            x4 = f[224 + lane];                           // x2[4]
        }

        float T[5][3];
        compute_T(ex[r], ey[r], ez[r], T);
        float e[3] = {ex[r], ey[r], ez[r]};
        float x1v[3] = {A.y, A.z, A.w};
        float x2v[5] = {X.x, X.y, X.z, X.w, x4};

#pragma unroll
        for (int k = 0; k < 3; k++) {
            a1a0[k] = fmaf(A.x, e[k], a1a0[k]);
            a1a1[k] = fmaf(f0b, e[k], a1a1[k]);
        }
#pragma unroll
        for (int i = 0; i < 3; i++) a0 = fmaf(x1v[i], e[i], a0);
#pragma unroll
        for (int a = 0; a < 5; a++)
#pragma unroll
            for (int i = 0; i < 3; i++) a2[a] = fmaf(x1v[i], T[a][i], a2[a]);
        if (lane < 16) {
#pragma unroll
            for (int a = 0; a < 5; a++)
#pragma unroll
                for (int k = 0; k < 3; k++) a1b[k] = fmaf(x2v[a], T[a][k], a1b[k]);
        }
    }

    __syncthreads();   // sWL ready

    // stage aggregates: [0,32) a0 | 32+3u+k (u<64) a1a | 224+3u+k (u<16) a1b | 272+5u+a a2
    float* ag = sag[warp];
    ag[lane] = a0;
#pragma unroll
    for (int k = 0; k < 3; k++) {
        ag[32 + 3 * lane + k]        = a1a0[k];
        ag[32 + 3 * (lane + 32) + k] = a1a1[k];
    }
    if (lane < 16) {
#pragma unroll
        for (int k = 0; k < 3; k++) ag[224 + 3 * lane + k] = a1b[k];
    }
#pragma unroll
    for (int a = 0; a < 5; a++) ag[272 + 5 * lane + a] = a2[a];
    __syncwarp();

    float* o = out + (size_t)node * DFEAT;
    {   // y0[w'] = sum_u a0[u] WL0[u,w']   (w' = 2lane, 2lane+1)
        float y0 = 0.f, y1v = 0.f;
#pragma unroll
        for (int u = 0; u < 32; u++) {
            float av = ag[u];
            y0  = fmaf(av, sWL0[u * 64 + 2 * lane],     y0);
            y1v = fmaf(av, sWL0[u * 64 + 2 * lane + 1], y1v);
        }
        o[2 * lane]     = y0;
        o[2 * lane + 1] = y1v;
    }
    {   // y1[w',k] = sum_{u<64} a1a[u,k] WL1a[u,w'] + sum_{u<16} a1b[u,k] WL1b[u,w']
        float y[3] = {0.f, 0.f, 0.f};
#pragma unroll
        for (int u = 0; u < 64; u++) {
            float lw = sWL1a[u * 32 + lane];
#pragma unroll
            for (int k = 0; k < 3; k++) y[k] = fmaf(ag[32 + 3 * u + k], lw, y[k]);
        }
#pragma unroll
        for (int u = 0; u < 16; u++) {
            float lw = sWL1b[u * 32 + lane];
#pragma unroll
            for (int k = 0; k < 3; k++) y[k] = fmaf(ag[224 + 3 * u + k], lw, y[k]);
        }
#pragma unroll
        for (int k = 0; k < 3; k++) o[64 + 3 * lane + k] = y[k];
    }
    if (lane < 16) {   // y2[w',a] = sum_u a2[u,a] WL2[u,w']
        float y[5] = {0.f, 0.f, 0.f, 0.f, 0.f};
#pragma unroll
        for (int u = 0; u < 32; u++) {
            float lw = sWL2[u * 16 + lane];
#pragma unroll
            for (int a = 0; a < 5; a++) y[a] = fmaf(ag[272 + 5 * u + a], lw, y[a]);
        }
#pragma unroll
        for (int a = 0; a < 5; a++) o[160 + 5 * lane + a] = y[a];
    }
}

// ============================================================================
extern "C" void kernel_launch(void* const* d_in, const int* in_sizes, int n_in,
                              void* d_out, int out_size) {
    const float* feats  = (const float*)d_in[0];  // (4,4096,240)
    const float* coords = (const float*)d_in[1];  // (4,4096,3)
    const float* W1 = (const float*)d_in[2];      // (64,32)
    const float* W2 = (const float*)d_in[3];      // (32,64)
    const float* W3 = (const float*)d_in[4];      // (32,16)
    const float* W4 = (const float*)d_in[5];      // (16,32)
    const float* L0 = (const float*)d_in[6];      // (64,64)
    const float* L1 = (const float*)d_in[7];      // (32,32)
    const float* L2 = (const float*)d_in[8];      // (16,16)
    float* out = (float*)d_out;

    repack_kernel<<<BN / 8, 256>>>(feats, coords, W1, W2, W3, W4, L0, L1, L2);
    knn_kernel<<<dim3(NNODES / KWARPS, NB), KTHREADS>>>();
    agg_kernel<<<BN / 8, 256>>>(out);
}